// round 1
// baseline (speedup 1.0000x reference)
#include <cuda_runtime.h>
#include <math.h>

#define BSZ  4096
#define HDIM 1024
#define NL1  28
#define NL2  280
#define NL3  2800

// Scratch (allocation-free rule: __device__ globals)
__device__ float g_z1[BSZ * NL1];
__device__ float g_z2[BSZ * NL2];
__device__ float g_z3[(size_t)BSZ * NL3];
__device__ float g_rowloss[BSZ];

// ---------------------------------------------------------------------------
// GEMM + bias + sigmoid:  Z = sigmoid(X @ W^T + b)
// X: [4096, 1024] row-major, W: [N, 1024] row-major (both K-major -> float4)
// Tile 128x128x16, 256 threads, 8x8 per thread.
// ---------------------------------------------------------------------------
__global__ __launch_bounds__(256) void gemm_sigmoid_kernel(
    const float* __restrict__ X,
    const float* __restrict__ W,
    const float* __restrict__ bias,
    int N, int which)
{
    float* __restrict__ Z = (which == 0) ? g_z1 : (which == 1) ? g_z2 : g_z3;

    __shared__ float As[16][128];
    __shared__ float Ws[16][128];

    const int tid = threadIdx.x;
    const int bm  = blockIdx.y * 128;
    const int bn  = blockIdx.x * 128;
    const int tx  = tid & 15;   // col group
    const int ty  = tid >> 4;   // row group

    float acc[8][8];
#pragma unroll
    for (int i = 0; i < 8; i++)
#pragma unroll
        for (int j = 0; j < 8; j++) acc[i][j] = 0.f;

    for (int k0 = 0; k0 < HDIM; k0 += 16) {
#pragma unroll
        for (int u = 0; u < 2; u++) {
            int f4 = tid + u * 256;      // 0..511
            int r  = f4 >> 2;            // 0..127 row in tile
            int c4 = f4 & 3;             // which float4 of the 16 cols
            float4 va = *(const float4*)(X + (size_t)(bm + r) * HDIM + k0 + c4 * 4);
            As[c4 * 4 + 0][r] = va.x;
            As[c4 * 4 + 1][r] = va.y;
            As[c4 * 4 + 2][r] = va.z;
            As[c4 * 4 + 3][r] = va.w;
            float4 vb = make_float4(0.f, 0.f, 0.f, 0.f);
            if (bn + r < N)
                vb = *(const float4*)(W + (size_t)(bn + r) * HDIM + k0 + c4 * 4);
            Ws[c4 * 4 + 0][r] = vb.x;
            Ws[c4 * 4 + 1][r] = vb.y;
            Ws[c4 * 4 + 2][r] = vb.z;
            Ws[c4 * 4 + 3][r] = vb.w;
        }
        __syncthreads();

#pragma unroll
        for (int k = 0; k < 16; k++) {
            float a[8], b[8];
#pragma unroll
            for (int i = 0; i < 8; i++) a[i] = As[k][ty * 8 + i];
#pragma unroll
            for (int j = 0; j < 8; j++) b[j] = Ws[k][tx * 8 + j];
#pragma unroll
            for (int i = 0; i < 8; i++)
#pragma unroll
                for (int j = 0; j < 8; j++)
                    acc[i][j] = fmaf(a[i], b[j], acc[i][j]);
        }
        __syncthreads();
    }

#pragma unroll
    for (int j = 0; j < 8; j++) {
        int n = bn + tx * 8 + j;
        if (n >= N) continue;
        float bv = bias[n];
#pragma unroll
        for (int i = 0; i < 8; i++) {
            int m   = bm + ty * 8 + i;
            float t = acc[i][j] + bv;
            Z[(size_t)m * N + n] = 1.f / (1.f + expf(-t));
        }
    }
}

// ---------------------------------------------------------------------------
// Per-row: build logits3 (path products), compute logsumexp for all 3 levels,
// write per-row loss contribution. One block per batch row. Deterministic.
// ---------------------------------------------------------------------------
__global__ __launch_bounds__(256) void path_loss_kernel(
    const int* __restrict__ labels,
    float* __restrict__ out_logits,   // may be nullptr
    int write_logits)
{
    const int b   = blockIdx.x;
    const int tid = threadIdx.x;

    __shared__ float s3[NL3];
    __shared__ float s2[NL2];
    __shared__ float s1[NL1];
    __shared__ float rm[256];
    __shared__ float rs[256];

    for (int k = tid; k < NL3; k += 256) s3[k] = g_z3[(size_t)b * NL3 + k];
    for (int k = tid; k < NL2; k += 256) s2[k] = g_z2[b * NL2 + k];
    if (tid < NL1) s1[tid] = g_z1[b * NL1 + tid];
    __syncthreads();

    float lse1v, lse2v, lse3v;

    // ---- level 3 ----
    {
        float m = -1e30f, s = 0.f;
        for (int k = tid; k < NL3; k += 256) {
            float l = s3[k / 100] * s3[k / 10] * s3[k];
            if (write_logits) out_logits[(size_t)b * NL3 + k] = l;
            float nm = fmaxf(m, l);
            s = s * expf(m - nm) + expf(l - nm);
            m = nm;
        }
        rm[tid] = m; rs[tid] = s;
        __syncthreads();
        for (int off = 128; off; off >>= 1) {
            if (tid < off) {
                float m2 = rm[tid + off], sv = rs[tid + off];
                float nm = fmaxf(rm[tid], m2);
                rs[tid] = rs[tid] * expf(rm[tid] - nm) + sv * expf(m2 - nm);
                rm[tid] = nm;
            }
            __syncthreads();
        }
        lse3v = rm[0] + logf(rs[0]);
        __syncthreads();
    }

    // ---- level 2 ----
    {
        float m = -1e30f, s = 0.f;
        for (int k = tid; k < NL2; k += 256) {
            float l = s2[k / 10] * s2[k];
            float nm = fmaxf(m, l);
            s = s * expf(m - nm) + expf(l - nm);
            m = nm;
        }
        rm[tid] = m; rs[tid] = s;
        __syncthreads();
        for (int off = 128; off; off >>= 1) {
            if (tid < off) {
                float m2 = rm[tid + off], sv = rs[tid + off];
                float nm = fmaxf(rm[tid], m2);
                rs[tid] = rs[tid] * expf(rm[tid] - nm) + sv * expf(m2 - nm);
                rm[tid] = nm;
            }
            __syncthreads();
        }
        lse2v = rm[0] + logf(rs[0]);
        __syncthreads();
    }

    // ---- level 1 ----
    {
        float m = -1e30f, s = 0.f;
        for (int k = tid; k < NL1; k += 256) {
            float l = s1[k];
            float nm = fmaxf(m, l);
            s = s * expf(m - nm) + expf(l - nm);
            m = nm;
        }
        rm[tid] = m; rs[tid] = s;
        __syncthreads();
        for (int off = 128; off; off >>= 1) {
            if (tid < off) {
                float m2 = rm[tid + off], sv = rs[tid + off];
                float nm = fmaxf(rm[tid], m2);
                rs[tid] = rs[tid] * expf(rm[tid] - nm) + sv * expf(m2 - nm);
                rm[tid] = nm;
            }
            __syncthreads();
        }
        lse1v = rm[0] + logf(rs[0]);
    }

    if (tid == 0) {
        int lab = labels[b];
        int a1 = lab / 100;
        int a2 = lab / 10;
        float l3 = s3[a1] * s3[a2] * s3[lab];
        float l2 = s2[a1] * s2[a2];   // logits2[a2] = z2[a2/10]*z2[a2], a2/10 == a1
        float l1 = s1[a1];
        g_rowloss[b] = (lse1v - l1) + (lse2v - l2) + (lse3v - l3);
    }
}

// ---------------------------------------------------------------------------
// Deterministic final reduction of per-row losses -> mean, into out[idx].
// ---------------------------------------------------------------------------
__global__ __launch_bounds__(1024) void loss_reduce_kernel(
    float* __restrict__ out, int idx)
{
    __shared__ float red[1024];
    int tid = threadIdx.x;
    float s = 0.f;
    for (int i = tid; i < BSZ; i += 1024) s += g_rowloss[i];
    red[tid] = s;
    __syncthreads();
    for (int off = 512; off; off >>= 1) {
        if (tid < off) red[tid] += red[tid + off];
        __syncthreads();
    }
    if (tid == 0) out[idx] = red[0] / (float)BSZ;
}

// ---------------------------------------------------------------------------
extern "C" void kernel_launch(void* const* d_in, const int* in_sizes, int n_in,
                              void* d_out, int out_size)
{
    const float* x      = (const float*)d_in[0];
    const int*   labels = (const int*)  d_in[1];
    const float* W1     = (const float*)d_in[2];
    const float* b1     = (const float*)d_in[3];
    const float* W2     = (const float*)d_in[4];
    const float* b2     = (const float*)d_in[5];
    const float* W3     = (const float*)d_in[6];
    const float* b3     = (const float*)d_in[7];
    float* out = (float*)d_out;

    dim3 blk(256);
    gemm_sigmoid_kernel<<<dim3((NL1 + 127) / 128, BSZ / 128), blk>>>(x, W1, b1, NL1, 0);
    gemm_sigmoid_kernel<<<dim3((NL2 + 127) / 128, BSZ / 128), blk>>>(x, W2, b2, NL2, 1);
    gemm_sigmoid_kernel<<<dim3((NL3 + 127) / 128, BSZ / 128), blk>>>(x, W3, b3, NL3, 2);

    const long long need = (long long)BSZ * NL3;   // 11,468,800
    int write_logits = (out_size >= need) ? 1 : 0;

    path_loss_kernel<<<BSZ, 256>>>(labels, write_logits ? out : nullptr, write_logits);

    if (out_size == 1) {
        loss_reduce_kernel<<<1, 1024>>>(out, 0);
    } else if ((long long)out_size >= need + 1) {
        loss_reduce_kernel<<<1, 1024>>>(out, (int)need);
    }
}

// round 2
// speedup vs baseline: 2.5119x; 2.5119x over previous
#include <cuda_runtime.h>
#include <math.h>
#include <stdint.h>

#define BSZ  4096
#define HDIM 1024
#define NL1  28
#define NL2  280
#define NL3  2800

// Scratch (allocation-free rule: __device__ globals)
__device__ float g_z1[BSZ * NL1];
__device__ float g_z2[BSZ * NL2];
__device__ float g_z3[(size_t)BSZ * NL3];
__device__ float g_rowloss[BSZ];

__device__ __forceinline__ float f2tf32(float x) {
    uint32_t u;
    asm("cvt.rna.tf32.f32 %0, %1;" : "=r"(u) : "f"(x));
    return __uint_as_float(u);
}

__device__ __forceinline__ float fast_sigmoid(float t) {
    float e = __expf(-t);
    return __fdividef(1.f, 1.f + e);
}

// ---------------------------------------------------------------------------
// tf32 tensor-core GEMM + bias + sigmoid:  Z = sigmoid(X @ W^T + b)
// X: [4096,1024] rm, W: [N,1024] rm. Tiles 128x128x16, 256 thr, 8 warps (2x4),
// warp tile 64x32, mma.m16n8k8.tf32. Smem m/n-major, row stride 20 floats
// (conflict-free fragment loads: banks = 20*g + t mod 32 all distinct).
// ---------------------------------------------------------------------------
#define BM 128
#define BN 128
#define BK 16
#define SKS 20

__global__ __launch_bounds__(256) void gemm_tf32_kernel(
    const float* __restrict__ X,
    const float* __restrict__ W,
    const float* __restrict__ bias,
    int N, int which)
{
    float* __restrict__ Z = (which == 0) ? g_z1 : (which == 1) ? g_z2 : g_z3;

    __shared__ __align__(16) float As[2][BM][SKS];
    __shared__ __align__(16) float Bs[2][BN][SKS];

    const int tid  = threadIdx.x;
    const int bm   = blockIdx.y * BM;
    const int bn   = blockIdx.x * BN;
    const int warp = tid >> 5;
    const int lane = tid & 31;
    const int g    = lane >> 2;      // groupID
    const int t    = lane & 3;       // threadID_in_group
    const int wm   = (warp >> 2) * 64;
    const int wn   = (warp & 3) * 32;

    const int r0 = tid >> 2;         // staging row (0..63), +64 for u=1
    const int c0 = tid & 3;          // staging float4 col (0..3)

    float acc[4][4][4];
#pragma unroll
    for (int mt = 0; mt < 4; mt++)
#pragma unroll
        for (int nt = 0; nt < 4; nt++)
#pragma unroll
            for (int c = 0; c < 4; c++) acc[mt][nt][c] = 0.f;

    float4 sa[2], sb[2];

    // prologue: load tile 0
#pragma unroll
    for (int u = 0; u < 2; u++) {
        int r = r0 + u * 64;
        sa[u] = *(const float4*)(X + (size_t)(bm + r) * HDIM + c0 * 4);
        if (bn + r < N)
            sb[u] = *(const float4*)(W + (size_t)(bn + r) * HDIM + c0 * 4);
        else
            sb[u] = make_float4(0.f, 0.f, 0.f, 0.f);
    }
#pragma unroll
    for (int u = 0; u < 2; u++) {
        int r = r0 + u * 64;
        float4 va, vb;
        va.x = f2tf32(sa[u].x); va.y = f2tf32(sa[u].y);
        va.z = f2tf32(sa[u].z); va.w = f2tf32(sa[u].w);
        vb.x = f2tf32(sb[u].x); vb.y = f2tf32(sb[u].y);
        vb.z = f2tf32(sb[u].z); vb.w = f2tf32(sb[u].w);
        *(float4*)&As[0][r][c0 * 4] = va;
        *(float4*)&Bs[0][r][c0 * 4] = vb;
    }
    __syncthreads();

    int buf = 0;
    const int NIT = HDIM / BK;   // 64
    for (int it = 1; it <= NIT; it++) {
        // preload next tile into regs (overlaps with MMA below)
        if (it < NIT) {
            int k0 = it * BK;
#pragma unroll
            for (int u = 0; u < 2; u++) {
                int r = r0 + u * 64;
                sa[u] = *(const float4*)(X + (size_t)(bm + r) * HDIM + k0 + c0 * 4);
                if (bn + r < N)
                    sb[u] = *(const float4*)(W + (size_t)(bn + r) * HDIM + k0 + c0 * 4);
                else
                    sb[u] = make_float4(0.f, 0.f, 0.f, 0.f);
            }
        }

        // compute current buffer
#pragma unroll
        for (int kk = 0; kk < BK; kk += 8) {
            uint32_t afr[4][4], bfr[4][2];
#pragma unroll
            for (int mt = 0; mt < 4; mt++) {
                int m0 = wm + mt * 16 + g;
                afr[mt][0] = __float_as_uint(As[buf][m0    ][kk + t    ]);
                afr[mt][1] = __float_as_uint(As[buf][m0 + 8][kk + t    ]);
                afr[mt][2] = __float_as_uint(As[buf][m0    ][kk + t + 4]);
                afr[mt][3] = __float_as_uint(As[buf][m0 + 8][kk + t + 4]);
            }
#pragma unroll
            for (int nt = 0; nt < 4; nt++) {
                int n0 = wn + nt * 8 + g;
                bfr[nt][0] = __float_as_uint(Bs[buf][n0][kk + t    ]);
                bfr[nt][1] = __float_as_uint(Bs[buf][n0][kk + t + 4]);
            }
#pragma unroll
            for (int mt = 0; mt < 4; mt++)
#pragma unroll
                for (int nt = 0; nt < 4; nt++) {
                    asm volatile(
                        "mma.sync.aligned.m16n8k8.row.col.f32.tf32.tf32.f32 "
                        "{%0,%1,%2,%3}, {%4,%5,%6,%7}, {%8,%9}, {%0,%1,%2,%3};"
                        : "+f"(acc[mt][nt][0]), "+f"(acc[mt][nt][1]),
                          "+f"(acc[mt][nt][2]), "+f"(acc[mt][nt][3])
                        : "r"(afr[mt][0]), "r"(afr[mt][1]),
                          "r"(afr[mt][2]), "r"(afr[mt][3]),
                          "r"(bfr[nt][0]), "r"(bfr[nt][1]));
                }
        }

        if (it < NIT) {
            int nb = buf ^ 1;
#pragma unroll
            for (int u = 0; u < 2; u++) {
                int r = r0 + u * 64;
                float4 va, vb;
                va.x = f2tf32(sa[u].x); va.y = f2tf32(sa[u].y);
                va.z = f2tf32(sa[u].z); va.w = f2tf32(sa[u].w);
                vb.x = f2tf32(sb[u].x); vb.y = f2tf32(sb[u].y);
                vb.z = f2tf32(sb[u].z); vb.w = f2tf32(sb[u].w);
                *(float4*)&As[nb][r][c0 * 4] = va;
                *(float4*)&Bs[nb][r][c0 * 4] = vb;
            }
            buf = nb;
            __syncthreads();
        }
    }

    // epilogue: bias + sigmoid, write Z
#pragma unroll
    for (int mt = 0; mt < 4; mt++) {
#pragma unroll
        for (int nt = 0; nt < 4; nt++) {
#pragma unroll
            for (int c = 0; c < 4; c++) {
                int m = bm + wm + mt * 16 + g + ((c >= 2) ? 8 : 0);
                int n = bn + wn + nt * 8 + 2 * t + (c & 1);
                if (n < N) {
                    float v = acc[mt][nt][c] + bias[n];
                    Z[(size_t)m * N + n] = fast_sigmoid(v);
                }
            }
        }
    }
}

// ---------------------------------------------------------------------------
// Per-row path products + losses. All logits are products of sigmoids, so
// logits in (0,1] -> NO max tracking needed for logsumexp (exp cannot
// overflow). One block per row, warp-shuffle reductions. Deterministic.
// ---------------------------------------------------------------------------
__global__ __launch_bounds__(256) void path_loss_kernel(
    const int* __restrict__ labels,
    float* __restrict__ out_logits,
    int write_logits)
{
    const int b    = blockIdx.x;
    const int tid  = threadIdx.x;
    const int lane = tid & 31;
    const int warp = tid >> 5;

    __shared__ float s3[NL3];
    __shared__ float s2[NL2];
    __shared__ float s1[NL1];
    __shared__ float red3[8], red2[8], red1[8];

    for (int k = tid; k < NL3; k += 256) s3[k] = g_z3[(size_t)b * NL3 + k];
    for (int k = tid; k < NL2; k += 256) s2[k] = g_z2[b * NL2 + k];
    if (tid < NL1) s1[tid] = g_z1[b * NL1 + tid];
    __syncthreads();

    // level 3
    float sum = 0.f;
    for (int k = tid; k < NL3; k += 256) {
        float l = s3[k / 100] * s3[k / 10] * s3[k];
        if (write_logits) out_logits[(size_t)b * NL3 + k] = l;
        sum += __expf(l);
    }
#pragma unroll
    for (int off = 16; off; off >>= 1) sum += __shfl_xor_sync(0xffffffffu, sum, off);
    if (lane == 0) red3[warp] = sum;

    // level 2
    sum = (tid < NL2) ? 0.f : 0.f;
    {
        float s = 0.f;
        for (int k = tid; k < NL2; k += 256) {
            float l = s2[k / 10] * s2[k];
            s += __expf(l);
        }
#pragma unroll
        for (int off = 16; off; off >>= 1) s += __shfl_xor_sync(0xffffffffu, s, off);
        if (lane == 0) red2[warp] = s;
    }

    // level 1
    {
        float s = (tid < NL1) ? __expf(s1[tid]) : 0.f;
#pragma unroll
        for (int off = 16; off; off >>= 1) s += __shfl_xor_sync(0xffffffffu, s, off);
        if (lane == 0) red1[warp] = s;
    }
    __syncthreads();

    if (tid == 0) {
        float t3 = 0.f, t2 = 0.f, t1 = 0.f;
#pragma unroll
        for (int w = 0; w < 8; w++) { t3 += red3[w]; t2 += red2[w]; t1 += red1[w]; }
        float lse3 = logf(t3);
        float lse2 = logf(t2);
        float lse1 = logf(t1);

        int lab = labels[b];
        int a1 = lab / 100;
        int a2 = lab / 10;
        float l3 = s3[a1] * s3[a2] * s3[lab];
        float l2 = s2[a1] * s2[a2];
        float l1 = s1[a1];
        g_rowloss[b] = (lse1 - l1) + (lse2 - l2) + (lse3 - l3);
    }
}

// ---------------------------------------------------------------------------
// Deterministic mean over per-row losses -> out[idx].
// ---------------------------------------------------------------------------
__global__ __launch_bounds__(1024) void loss_reduce_kernel(
    float* __restrict__ out, int idx)
{
    __shared__ float red[1024];
    int tid = threadIdx.x;
    float s = 0.f;
    for (int i = tid; i < BSZ; i += 1024) s += g_rowloss[i];
    red[tid] = s;
    __syncthreads();
    for (int off = 512; off; off >>= 1) {
        if (tid < off) red[tid] += red[tid + off];
        __syncthreads();
    }
    if (tid == 0) out[idx] = red[0] / (float)BSZ;
}

// ---------------------------------------------------------------------------
extern "C" void kernel_launch(void* const* d_in, const int* in_sizes, int n_in,
                              void* d_out, int out_size)
{
    const float* x      = (const float*)d_in[0];
    const int*   labels = (const int*)  d_in[1];
    const float* W1     = (const float*)d_in[2];
    const float* b1     = (const float*)d_in[3];
    const float* W2     = (const float*)d_in[4];
    const float* b2     = (const float*)d_in[5];
    const float* W3     = (const float*)d_in[6];
    const float* b3     = (const float*)d_in[7];
    float* out = (float*)d_out;

    dim3 blk(256);
    gemm_tf32_kernel<<<dim3((NL1 + BN - 1) / BN, BSZ / BM), blk>>>(x, W1, b1, NL1, 0);
    gemm_tf32_kernel<<<dim3((NL2 + BN - 1) / BN, BSZ / BM), blk>>>(x, W2, b2, NL2, 1);
    gemm_tf32_kernel<<<dim3((NL3 + BN - 1) / BN, BSZ / BM), blk>>>(x, W3, b3, NL3, 2);

    const long long need = (long long)BSZ * NL3;
    int write_logits = (out_size >= need) ? 1 : 0;

    path_loss_kernel<<<BSZ, 256>>>(labels, write_logits ? out : nullptr, write_logits);

    if (out_size == 1) {
        loss_reduce_kernel<<<1, 1024>>>(out, 0);
    } else if ((long long)out_size >= need + 1) {
        loss_reduce_kernel<<<1, 1024>>>(out, (int)need);
    }
}

// round 5
// speedup vs baseline: 3.6026x; 1.4342x over previous
#include <cuda_runtime.h>
#include <math.h>
#include <stdint.h>

#define BSZ  4096
#define HDIM 1024
#define NL1  28
#define NL2  280
#define NL3  2800

// Padded weight rows: 128 (L1) + 384 (L2) + 2816 (L3)
#define PR1   128
#define PR2   384
#define PR3   2816
#define PROWS (PR1 + PR2 + PR3)   // 3328

// Scratch (__device__ globals; allocation-free rule)
__device__ float g_xc[(size_t)BSZ * HDIM];       // tf32-rounded X
__device__ float g_wp[(size_t)PROWS * HDIM];     // tf32-rounded, padded W
__device__ float g_bp[PROWS];                    // padded bias
__device__ float g_z1[BSZ * NL1];
__device__ float g_z2[BSZ * NL2];
__device__ float g_z3[(size_t)BSZ * NL3];
__device__ float g_rowloss[BSZ];

__device__ __forceinline__ float f2tf32(float x) {
    uint32_t u;
    asm("cvt.rna.tf32.f32 %0, %1;" : "=r"(u) : "f"(x));
    return __uint_as_float(u);
}
__device__ __forceinline__ float4 f2tf32_4(float4 v) {
    v.x = f2tf32(v.x); v.y = f2tf32(v.y); v.z = f2tf32(v.z); v.w = f2tf32(v.w);
    return v;
}
__device__ __forceinline__ float fast_sigmoid(float t) {
    return __fdividef(1.f, 1.f + __expf(-t));
}

// ---------------------------------------------------------------------------
// Conversion kernel: X -> g_xc (tf32 RNA), {W1,W2,W3} -> g_wp (tf32, padded,
// zero rows in padding), {b1,b2,b3} -> g_bp. One grid-stride-free launch.
// ---------------------------------------------------------------------------
#define NX4 (BSZ * HDIM / 4)        // 1048576
#define NW4 (PROWS * HDIM / 4)      // 851968
#define H4  (HDIM / 4)              // 256

__global__ __launch_bounds__(256) void convert_kernel(
    const float* __restrict__ X,
    const float* __restrict__ W1, const float* __restrict__ W2,
    const float* __restrict__ W3,
    const float* __restrict__ b1, const float* __restrict__ b2,
    const float* __restrict__ b3)
{
    int gid = blockIdx.x * 256 + threadIdx.x;

    if (gid < NX4) {
        float4 v = ((const float4*)X)[gid];
        ((float4*)g_xc)[gid] = f2tf32_4(v);
    } else if (gid < NX4 + NW4) {
        int wi = gid - NX4;
        int pr = wi / H4;           // padded row
        int c  = wi - pr * H4;      // float4 col
        float4 v = make_float4(0.f, 0.f, 0.f, 0.f);
        if (pr < PR1) {
            if (pr < NL1) v = ((const float4*)W1)[pr * H4 + c];
        } else if (pr < PR1 + PR2) {
            int r = pr - PR1;
            if (r < NL2) v = ((const float4*)W2)[r * H4 + c];
        } else {
            int r = pr - PR1 - PR2;
            if (r < NL3) v = ((const float4*)W3)[(size_t)r * H4 + c];
        }
        ((float4*)g_wp)[wi] = f2tf32_4(v);
    }

    if (gid < PROWS) {
        float b = 0.f;
        if (gid < PR1) {
            if (gid < NL1) b = b1[gid];
        } else if (gid < PR1 + PR2) {
            int r = gid - PR1;
            if (r < NL2) b = b2[r];
        } else {
            int r = gid - PR1 - PR2;
            if (r < NL3) b = b3[r];
        }
        g_bp[gid] = b;
    }
}

// ---------------------------------------------------------------------------
// Fused tf32 tensor GEMM + bias + sigmoid for all three levels.
// Tiles 128x128x16, 256 threads, warp tile 64x32, mma.m16n8k8.tf32.
// 3-stage cp.async pipeline, no predicates (inputs pre-padded).
// Smem rows stride 20 floats -> conflict-free fragment loads.
// ---------------------------------------------------------------------------
#define BM 128
#define BN 128
#define BK 16
#define SKS 20
#define STAGE_F (2 * 128 * SKS)     // floats per stage (A then B): 5120
#define SMEM_BYTES (3 * STAGE_F * 4)  // 61440

#define CP_ASYNC16(dst_u32, src_ptr) \
    asm volatile("cp.async.cg.shared.global [%0], [%1], 16;" :: "r"(dst_u32), "l"(src_ptr))

__global__ __launch_bounds__(256, 2) void gemm_fused_kernel()
{
    extern __shared__ float sm[];

    const int tile = blockIdx.x;      // 0..25
    int bn, woff, N;
    float* __restrict__ Z;
    if (tile == 0)      { bn = 0;              woff = 0;         N = NL1; Z = g_z1; }
    else if (tile < 4)  { bn = (tile - 1) * BN; woff = PR1;       N = NL2; Z = g_z2; }
    else                { bn = (tile - 4) * BN; woff = PR1 + PR2; N = NL3; Z = g_z3; }

    const int bm   = blockIdx.y * BM;
    const int tid  = threadIdx.x;
    const int warp = tid >> 5;
    const int lane = tid & 31;
    const int g    = lane >> 2;
    const int t    = lane & 3;
    const int wm   = (warp >> 2) * 64;
    const int wn   = (warp & 3) * 32;

    const float* __restrict__ Xt = g_xc + (size_t)bm * HDIM;
    const float* __restrict__ Wt = g_wp + (size_t)(woff + bn) * HDIM;

    const uint32_t sbase = (uint32_t)__cvta_generic_to_shared(sm);

    // cp.async mapping: per matrix, 2 chunks per thread
    const int r0 = tid >> 2;          // 0..63 (+64 for u=1)
    const int c0 = tid & 3;           // float4 chunk in the 16-wide k slab

    float acc[4][4][4];
#pragma unroll
    for (int mt = 0; mt < 4; mt++)
#pragma unroll
        for (int nt = 0; nt < 4; nt++)
#pragma unroll
            for (int c = 0; c < 4; c++) acc[mt][nt][c] = 0.f;

    // ---- issue a stage's loads ----
    auto issue_stage = [&](int buf, int k0) {
        uint32_t so = sbase + (uint32_t)(buf * STAGE_F) * 4u;
#pragma unroll
        for (int u = 0; u < 2; u++) {
            int r = r0 + u * 64;
            uint32_t da = so + (uint32_t)(r * SKS + c0 * 4) * 4u;
            CP_ASYNC16(da, Xt + (size_t)r * HDIM + k0 + c0 * 4);
            uint32_t db = so + (uint32_t)(2560 + r * SKS + c0 * 4) * 4u;
            CP_ASYNC16(db, Wt + (size_t)r * HDIM + k0 + c0 * 4);
        }
    };

    issue_stage(0, 0);
    asm volatile("cp.async.commit_group;");
    issue_stage(1, BK);
    asm volatile("cp.async.commit_group;");

    const int NIT = HDIM / BK;        // 64
    for (int it = 0; it < NIT; it++) {
        asm volatile("cp.async.wait_group 1;");
        __syncthreads();

        if (it + 2 < NIT) issue_stage((it + 2) % 3, (it + 2) * BK);
        asm volatile("cp.async.commit_group;");

        const float* A = sm + (it % 3) * STAGE_F;
        const float* B = A + 2560;

#pragma unroll
        for (int kk = 0; kk < BK; kk += 8) {
            uint32_t afr[4][4], bfr[4][2];
#pragma unroll
            for (int mt = 0; mt < 4; mt++) {
                int m0 = wm + mt * 16 + g;
                afr[mt][0] = __float_as_uint(A[m0 * SKS + kk + t]);
                afr[mt][1] = __float_as_uint(A[(m0 + 8) * SKS + kk + t]);
                afr[mt][2] = __float_as_uint(A[m0 * SKS + kk + t + 4]);
                afr[mt][3] = __float_as_uint(A[(m0 + 8) * SKS + kk + t + 4]);
            }
#pragma unroll
            for (int nt = 0; nt < 4; nt++) {
                int n0 = wn + nt * 8 + g;
                bfr[nt][0] = __float_as_uint(B[n0 * SKS + kk + t]);
                bfr[nt][1] = __float_as_uint(B[n0 * SKS + kk + t + 4]);
            }
#pragma unroll
            for (int mt = 0; mt < 4; mt++)
#pragma unroll
                for (int nt = 0; nt < 4; nt++) {
                    asm volatile(
                        "mma.sync.aligned.m16n8k8.row.col.f32.tf32.tf32.f32 "
                        "{%0,%1,%2,%3}, {%4,%5,%6,%7}, {%8,%9}, {%0,%1,%2,%3};"
                        : "+f"(acc[mt][nt][0]), "+f"(acc[mt][nt][1]),
                          "+f"(acc[mt][nt][2]), "+f"(acc[mt][nt][3])
                        : "r"(afr[mt][0]), "r"(afr[mt][1]),
                          "r"(afr[mt][2]), "r"(afr[mt][3]),
                          "r"(bfr[nt][0]), "r"(bfr[nt][1]));
                }
        }
    }

    // epilogue: bias + sigmoid
    const float* __restrict__ bt = g_bp + woff + bn;
#pragma unroll
    for (int mt = 0; mt < 4; mt++) {
#pragma unroll
        for (int nt = 0; nt < 4; nt++) {
#pragma unroll
            for (int c = 0; c < 4; c++) {
                int m  = bm + wm + mt * 16 + g + ((c >= 2) ? 8 : 0);
                int nl = wn + nt * 8 + 2 * t + (c & 1);
                int n  = bn + nl;
                if (n < N) {
                    float v = acc[mt][nt][c] + bt[nl];
                    Z[(size_t)m * N + n] = fast_sigmoid(v);
                }
            }
        }
    }
}

// ---------------------------------------------------------------------------
// Per-row path products + losses. Logits in (0,1] -> plain sum-exp is safe.
// float4 loads/stores. One block per row. Deterministic.
// ---------------------------------------------------------------------------
__global__ __launch_bounds__(256) void path_loss_kernel(
    const int* __restrict__ labels,
    float* __restrict__ out_logits,
    int write_logits)
{
    const int b    = blockIdx.x;
    const int tid  = threadIdx.x;
    const int lane = tid & 31;
    const int warp = tid >> 5;

    __shared__ float s3[NL3];
    __shared__ float s2[NL2];
    __shared__ float s1[NL1];
    __shared__ float red3[8], red2[8], red1[8];

    for (int k4 = tid; k4 < NL3 / 4; k4 += 256)
        ((float4*)s3)[k4] = ((const float4*)(g_z3 + (size_t)b * NL3))[k4];
    if (tid < NL2 / 4)
        ((float4*)s2)[tid] = ((const float4*)(g_z2 + b * NL2))[tid];
    if (tid < NL1)
        s1[tid] = g_z1[b * NL1 + tid];
    __syncthreads();

    // level 3
    float sum3 = 0.f;
    for (int k4 = tid; k4 < NL3 / 4; k4 += 256) {
        int k = k4 * 4;
        float4 zk = ((const float4*)s3)[k4];
        float4 l;
        l.x = s3[k / 100]       * s3[k / 10]       * zk.x;
        l.y = s3[(k + 1) / 100] * s3[(k + 1) / 10] * zk.y;
        l.z = s3[(k + 2) / 100] * s3[(k + 2) / 10] * zk.z;
        l.w = s3[(k + 3) / 100] * s3[(k + 3) / 10] * zk.w;
        if (write_logits)
            ((float4*)(out_logits + (size_t)b * NL3))[k4] = l;
        sum3 += __expf(l.x) + __expf(l.y) + __expf(l.z) + __expf(l.w);
    }
#pragma unroll
    for (int off = 16; off; off >>= 1) sum3 += __shfl_xor_sync(0xffffffffu, sum3, off);
    if (lane == 0) red3[warp] = sum3;

    // level 2
    {
        float s = 0.f;
        if (tid < NL2 / 4) {
            int k = tid * 4;
            float4 zk = ((const float4*)s2)[tid];
            s = __expf(s2[k / 10] * zk.x) + __expf(s2[(k + 1) / 10] * zk.y) +
                __expf(s2[(k + 2) / 10] * zk.z) + __expf(s2[(k + 3) / 10] * zk.w);
        }
#pragma unroll
        for (int off = 16; off; off >>= 1) s += __shfl_xor_sync(0xffffffffu, s, off);
        if (lane == 0) red2[warp] = s;
    }

    // level 1
    {
        float s = (tid < NL1) ? __expf(s1[tid]) : 0.f;
#pragma unroll
        for (int off = 16; off; off >>= 1) s += __shfl_xor_sync(0xffffffffu, s, off);
        if (lane == 0) red1[warp] = s;
    }
    __syncthreads();

    if (tid == 0) {
        float t3 = 0.f, t2 = 0.f, t1 = 0.f;
#pragma unroll
        for (int w = 0; w < 8; w++) { t3 += red3[w]; t2 += red2[w]; t1 += red1[w]; }
        int lab = labels[b];
        int a1 = lab / 100;
        int a2 = lab / 10;
        float l3 = s3[a1] * s3[a2] * s3[lab];
        float l2 = s2[a1] * s2[a2];
        float l1 = s1[a1];
        g_rowloss[b] = (logf(t1) - l1) + (logf(t2) - l2) + (logf(t3) - l3);
    }
}

// ---------------------------------------------------------------------------
__global__ __launch_bounds__(1024) void loss_reduce_kernel(
    float* __restrict__ out, int idx)
{
    __shared__ float red[1024];
    int tid = threadIdx.x;
    float s = 0.f;
    for (int i = tid; i < BSZ; i += 1024) s += g_rowloss[i];
    red[tid] = s;
    __syncthreads();
    for (int off = 512; off; off >>= 1) {
        if (tid < off) red[tid] += red[tid + off];
        __syncthreads();
    }
    if (tid == 0) out[idx] = red[0] / (float)BSZ;
}

// ---------------------------------------------------------------------------
extern "C" void kernel_launch(void* const* d_in, const int* in_sizes, int n_in,
                              void* d_out, int out_size)
{
    const float* x      = (const float*)d_in[0];
    const int*   labels = (const int*)  d_in[1];
    const float* W1     = (const float*)d_in[2];
    const float* b1     = (const float*)d_in[3];
    const float* W2     = (const float*)d_in[4];
    const float* b2     = (const float*)d_in[5];
    const float* W3     = (const float*)d_in[6];
    const float* b3     = (const float*)d_in[7];
    float* out = (float*)d_out;

    static int smem_set = 0;
    if (!smem_set) {
        cudaFuncSetAttribute(gemm_fused_kernel,
                             cudaFuncAttributeMaxDynamicSharedMemorySize, SMEM_BYTES);
        smem_set = 1;
    }

    int conv_blocks = (NX4 + NW4 + 255) / 256;
    convert_kernel<<<conv_blocks, 256>>>(x, W1, W2, W3, b1, b2, b3);

    gemm_fused_kernel<<<dim3(26, BSZ / BM), 256, SMEM_BYTES>>>();

    const long long need = (long long)BSZ * NL3;
    int write_logits = (out_size >= need) ? 1 : 0;
    path_loss_kernel<<<BSZ, 256>>>(labels, write_logits ? out : nullptr, write_logits);

    if (out_size == 1) {
        loss_reduce_kernel<<<1, 1024>>>(out, 0);
    } else if ((long long)out_size >= need + 1) {
        loss_reduce_kernel<<<1, 1024>>>(out, (int)need);
    }
}

// round 12
// speedup vs baseline: 5.9414x; 1.6492x over previous
#include <cuda_runtime.h>
#include <cuda_fp16.h>
#include <math.h>
#include <stdint.h>

#define BSZ  4096
#define HDIM 1024
#define NL1  28
#define NL2  280
#define NL3  2800

// Padded weight rows: 128 (L1) + 384 (L2) + 2816 (L3)
#define PR1   128
#define PR2   384
#define PR3   2816
#define PROWS (PR1 + PR2 + PR3)   // 3328

// Scratch (__device__ globals; allocation-free rule)
__device__ __half g_xh[(size_t)BSZ * HDIM];      // fp16 X
__device__ __half g_wh[(size_t)PROWS * HDIM];    // fp16 padded W
__device__ float  g_bp[PROWS];                   // padded bias (fp32)
__device__ float  g_z1[BSZ * NL1];
__device__ float  g_z2[BSZ * NL2];
__device__ float  g_z3[(size_t)BSZ * NL3];
__device__ float  g_rowloss[BSZ];

__device__ __forceinline__ float fast_sigmoid(float t) {
    return __fdividef(1.f, 1.f + __expf(-t));
}

// ---------------------------------------------------------------------------
// Conversion: X -> g_xh (fp16 RN), {W1,W2,W3} -> g_wh (fp16, padded with 0),
// {b1,b2,b3} -> g_bp. One float4 (-> 4 halves = 8B) per thread slot.
// ---------------------------------------------------------------------------
#define NX4 (BSZ * HDIM / 4)        // 1048576
#define NW4 (PROWS * HDIM / 4)      // 851968
#define H4  (HDIM / 4)              // 256

__device__ __forceinline__ void store_h4(__half* dst, float4 v) {
    __half2 lo = __floats2half2_rn(v.x, v.y);
    __half2 hi = __floats2half2_rn(v.z, v.w);
    uint2 p;
    p.x = *(uint32_t*)&lo;
    p.y = *(uint32_t*)&hi;
    *(uint2*)dst = p;
}

__global__ __launch_bounds__(256) void convert_kernel(
    const float* __restrict__ X,
    const float* __restrict__ W1, const float* __restrict__ W2,
    const float* __restrict__ W3,
    const float* __restrict__ b1, const float* __restrict__ b2,
    const float* __restrict__ b3)
{
    int gid = blockIdx.x * 256 + threadIdx.x;

    if (gid < NX4) {
        float4 v = ((const float4*)X)[gid];
        store_h4(g_xh + (size_t)gid * 4, v);
    } else if (gid < NX4 + NW4) {
        int wi = gid - NX4;
        int pr = wi / H4;
        int c  = wi - pr * H4;
        float4 v = make_float4(0.f, 0.f, 0.f, 0.f);
        if (pr < PR1) {
            if (pr < NL1) v = ((const float4*)W1)[pr * H4 + c];
        } else if (pr < PR1 + PR2) {
            int r = pr - PR1;
            if (r < NL2) v = ((const float4*)W2)[r * H4 + c];
        } else {
            int r = pr - PR1 - PR2;
            if (r < NL3) v = ((const float4*)W3)[(size_t)r * H4 + c];
        }
        store_h4(g_wh + (size_t)wi * 4, v);
    }

    if (gid < PROWS) {
        float b = 0.f;
        if (gid < PR1) {
            if (gid < NL1) b = b1[gid];
        } else if (gid < PR1 + PR2) {
            int r = gid - PR1;
            if (r < NL2) b = b2[r];
        } else {
            int r = gid - PR1 - PR2;
            if (r < NL3) b = b3[r];
        }
        g_bp[gid] = b;
    }
}

// ---------------------------------------------------------------------------
// Fused fp16 tensor GEMM + bias + sigmoid for all three levels.
// Tiles 128x128x32(halves), 256 threads, warp tile 64x32,
// mma.m16n8k16.f32.f16.f16.f32 (2 k-steps per stage).
// 3-stage cp.async pipeline, inputs pre-padded (no predicates).
// Smem rows stride 40 halves (80B): half2 fragment loads conflict-free
// (word = 20*g + t mod 32, all 32 distinct).
// ---------------------------------------------------------------------------
#define BM 128
#define BN 128
#define BK 32                         // halves per stage in k
#define SKS 40                        // smem row stride in halves
#define STAGE_H (2 * 128 * SKS)       // halves per stage (A then B): 10240
#define STAGE_BYTES (STAGE_H * 2)     // 20480
#define SMEM_BYTES (3 * STAGE_BYTES)  // 61440
#define B_OFF_H (128 * SKS)           // B start within stage (halves): 5120

#define CP_ASYNC16(dst_u32, src_ptr) \
    asm volatile("cp.async.cg.shared.global [%0], [%1], 16;" :: "r"(dst_u32), "l"(src_ptr))

__global__ __launch_bounds__(256, 2) void gemm_fused_kernel()
{
    extern __shared__ __half sm[];

    const int tile = blockIdx.x;      // 0..25
    int bn, woff, N;
    float* __restrict__ Z;
    if (tile == 0)      { bn = 0;               woff = 0;         N = NL1; Z = g_z1; }
    else if (tile < 4)  { bn = (tile - 1) * BN; woff = PR1;       N = NL2; Z = g_z2; }
    else                { bn = (tile - 4) * BN; woff = PR1 + PR2; N = NL3; Z = g_z3; }

    const int bm   = blockIdx.y * BM;
    const int tid  = threadIdx.x;
    const int warp = tid >> 5;
    const int lane = tid & 31;
    const int g    = lane >> 2;
    const int t    = lane & 3;
    const int wm   = (warp >> 2) * 64;
    const int wn   = (warp & 3) * 32;

    const __half* __restrict__ Xt = g_xh + (size_t)bm * HDIM;
    const __half* __restrict__ Wt = g_wh + (size_t)(woff + bn) * HDIM;

    const uint32_t sbase = (uint32_t)__cvta_generic_to_shared(sm);

    // cp.async mapping: 1024 16B-chunks per stage (A 512 + B 512), 4 per thread
    const int r0 = tid >> 2;          // 0..63
    const int c0 = tid & 3;           // 16B chunk in the 32-half k slab (4 chunks)

    float acc[4][4][4];
#pragma unroll
    for (int mt = 0; mt < 4; mt++)
#pragma unroll
        for (int nt = 0; nt < 4; nt++)
#pragma unroll
            for (int c = 0; c < 4; c++) acc[mt][nt][c] = 0.f;

    auto issue_stage = [&](int buf, int k0) {
        uint32_t so = sbase + (uint32_t)buf * STAGE_BYTES;
#pragma unroll
        for (int u = 0; u < 2; u++) {
            int r = r0 + u * 64;
            // A row r: smem byte off = r*80 + c0*16 ; gmem: Xt + r*HDIM + k0 + c0*8
            CP_ASYNC16(so + (uint32_t)(r * 80 + c0 * 16),
                       Xt + (size_t)r * HDIM + k0 + c0 * 8);
            CP_ASYNC16(so + (uint32_t)(B_OFF_H * 2 + r * 80 + c0 * 16),
                       Wt + (size_t)r * HDIM + k0 + c0 * 8);
        }
    };

    issue_stage(0, 0);
    asm volatile("cp.async.commit_group;");
    issue_stage(1, BK);
    asm volatile("cp.async.commit_group;");

    const int NIT = HDIM / BK;        // 32
    for (int it = 0; it < NIT; it++) {
        asm volatile("cp.async.wait_group 1;");
        __syncthreads();

        if (it + 2 < NIT) issue_stage((it + 2) % 3, (it + 2) * BK);
        asm volatile("cp.async.commit_group;");

        const __half* A = sm + (it % 3) * STAGE_H;
        const __half* B = A + B_OFF_H;

#pragma unroll
        for (int kk = 0; kk < BK; kk += 16) {
            uint32_t afr[4][4], bfr[4][2];
#pragma unroll
            for (int mt = 0; mt < 4; mt++) {
                int m0 = wm + mt * 16 + g;
                afr[mt][0] = *(const uint32_t*)&A[m0 * SKS + kk + 2 * t];
                afr[mt][1] = *(const uint32_t*)&A[(m0 + 8) * SKS + kk + 2 * t];
                afr[mt][2] = *(const uint32_t*)&A[m0 * SKS + kk + 2 * t + 8];
                afr[mt][3] = *(const uint32_t*)&A[(m0 + 8) * SKS + kk + 2 * t + 8];
            }
#pragma unroll
            for (int nt = 0; nt < 4; nt++) {
                int n0 = wn + nt * 8 + g;
                bfr[nt][0] = *(const uint32_t*)&B[n0 * SKS + kk + 2 * t];
                bfr[nt][1] = *(const uint32_t*)&B[n0 * SKS + kk + 2 * t + 8];
            }
#pragma unroll
            for (int mt = 0; mt < 4; mt++)
#pragma unroll
                for (int nt = 0; nt < 4; nt++) {
                    asm volatile(
                        "mma.sync.aligned.m16n8k16.row.col.f32.f16.f16.f32 "
                        "{%0,%1,%2,%3}, {%4,%5,%6,%7}, {%8,%9}, {%0,%1,%2,%3};"
                        : "+f"(acc[mt][nt][0]), "+f"(acc[mt][nt][1]),
                          "+f"(acc[mt][nt][2]), "+f"(acc[mt][nt][3])
                        : "r"(afr[mt][0]), "r"(afr[mt][1]),
                          "r"(afr[mt][2]), "r"(afr[mt][3]),
                          "r"(bfr[nt][0]), "r"(bfr[nt][1]));
                }
        }
    }

    // epilogue: bias + sigmoid
    const float* __restrict__ bt = g_bp + woff + bn;
#pragma unroll
    for (int mt = 0; mt < 4; mt++) {
#pragma unroll
        for (int nt = 0; nt < 4; nt++) {
#pragma unroll
            for (int c = 0; c < 4; c++) {
                int m  = bm + wm + mt * 16 + g + ((c >= 2) ? 8 : 0);
                int nl = wn + nt * 8 + 2 * t + (c & 1);
                int n  = bn + nl;
                if (n < N) {
                    float v = acc[mt][nt][c] + bt[nl];
                    Z[(size_t)m * N + n] = fast_sigmoid(v);
                }
            }
        }
    }
}

// ---------------------------------------------------------------------------
// Per-row path products + losses (logits in (0,1] -> plain sum-exp safe).
// ---------------------------------------------------------------------------
__global__ __launch_bounds__(256) void path_loss_kernel(
    const int* __restrict__ labels,
    float* __restrict__ out_logits,
    int write_logits)
{
    const int b    = blockIdx.x;
    const int tid  = threadIdx.x;
    const int lane = tid & 31;
    const int warp = tid >> 5;

    __shared__ float s3[NL3];
    __shared__ float s2[NL2];
    __shared__ float s1[NL1];
    __shared__ float red3[8], red2[8], red1[8];

    for (int k4 = tid; k4 < NL3 / 4; k4 += 256)
        ((float4*)s3)[k4] = ((const float4*)(g_z3 + (size_t)b * NL3))[k4];
    if (tid < NL2 / 4)
        ((float4*)s2)[tid] = ((const float4*)(g_z2 + b * NL2))[tid];
    if (tid < NL1)
        s1[tid] = g_z1[b * NL1 + tid];
    __syncthreads();

    float sum3 = 0.f;
    for (int k4 = tid; k4 < NL3 / 4; k4 += 256) {
        int k = k4 * 4;
        float4 zk = ((const float4*)s3)[k4];
        float4 l;
        l.x = s3[k / 100]       * s3[k / 10]       * zk.x;
        l.y = s3[(k + 1) / 100] * s3[(k + 1) / 10] * zk.y;
        l.z = s3[(k + 2) / 100] * s3[(k + 2) / 10] * zk.z;
        l.w = s3[(k + 3) / 100] * s3[(k + 3) / 10] * zk.w;
        if (write_logits)
            ((float4*)(out_logits + (size_t)b * NL3))[k4] = l;
        sum3 += __expf(l.x) + __expf(l.y) + __expf(l.z) + __expf(l.w);
    }
#pragma unroll
    for (int off = 16; off; off >>= 1) sum3 += __shfl_xor_sync(0xffffffffu, sum3, off);
    if (lane == 0) red3[warp] = sum3;

    {
        float s = 0.f;
        if (tid < NL2 / 4) {
            int k = tid * 4;
            float4 zk = ((const float4*)s2)[tid];
            s = __expf(s2[k / 10] * zk.x) + __expf(s2[(k + 1) / 10] * zk.y) +
                __expf(s2[(k + 2) / 10] * zk.z) + __expf(s2[(k + 3) / 10] * zk.w);
        }
#pragma unroll
        for (int off = 16; off; off >>= 1) s += __shfl_xor_sync(0xffffffffu, s, off);
        if (lane == 0) red2[warp] = s;
    }
    {
        float s = (tid < NL1) ? __expf(s1[tid]) : 0.f;
#pragma unroll
        for (int off = 16; off; off >>= 1) s += __shfl_xor_sync(0xffffffffu, s, off);
        if (lane == 0) red1[warp] = s;
    }
    __syncthreads();

    if (tid == 0) {
        float t3 = 0.f, t2 = 0.f, t1 = 0.f;
#pragma unroll
        for (int w = 0; w < 8; w++) { t3 += red3[w]; t2 += red2[w]; t1 += red1[w]; }
        int lab = labels[b];
        int a1 = lab / 100;
        int a2 = lab / 10;
        float l3 = s3[a1] * s3[a2] * s3[lab];
        float l2 = s2[a1] * s2[a2];
        float l1 = s1[a1];
        g_rowloss[b] = (logf(t1) - l1) + (logf(t2) - l2) + (logf(t3) - l3);
    }
}

// ---------------------------------------------------------------------------
__global__ __launch_bounds__(1024) void loss_reduce_kernel(
    float* __restrict__ out, int idx)
{
    __shared__ float red[1024];
    int tid = threadIdx.x;
    float s = 0.f;
    for (int i = tid; i < BSZ; i += 1024) s += g_rowloss[i];
    red[tid] = s;
    __syncthreads();
    for (int off = 512; off; off >>= 1) {
        if (tid < off) red[tid] += red[tid + off];
        __syncthreads();
    }
    if (tid == 0) out[idx] = red[0] / (float)BSZ;
}

// ---------------------------------------------------------------------------
extern "C" void kernel_launch(void* const* d_in, const int* in_sizes, int n_in,
                              void* d_out, int out_size)
{
    const float* x      = (const float*)d_in[0];
    const int*   labels = (const int*)  d_in[1];
    const float* W1     = (const float*)d_in[2];
    const float* b1     = (const float*)d_in[3];
    const float* W2     = (const float*)d_in[4];
    const float* b2     = (const float*)d_in[5];
    const float* W3     = (const float*)d_in[6];
    const float* b3     = (const float*)d_in[7];
    float* out = (float*)d_out;

    static int smem_set = 0;
    if (!smem_set) {
        cudaFuncSetAttribute(gemm_fused_kernel,
                             cudaFuncAttributeMaxDynamicSharedMemorySize, SMEM_BYTES);
        smem_set = 1;
    }

    int conv_blocks = (NX4 + NW4 + 255) / 256;
    convert_kernel<<<conv_blocks, 256>>>(x, W1, W2, W3, b1, b2, b3);

    gemm_fused_kernel<<<dim3(26, BSZ / BM), 256, SMEM_BYTES>>>();

    const long long need = (long long)BSZ * NL3;
    int write_logits = (out_size >= need) ? 1 : 0;
    path_loss_kernel<<<BSZ, 256>>>(labels, write_logits ? out : nullptr, write_logits);

    if (out_size == 1) {
        loss_reduce_kernel<<<1, 1024>>>(out, 0);
    } else if ((long long)out_size >= need + 1) {
        loss_reduce_kernel<<<1, 1024>>>(out, (int)need);
    }
}

// round 13
// speedup vs baseline: 6.2211x; 1.0471x over previous
#include <cuda_runtime.h>
#include <cuda_fp16.h>
#include <math.h>
#include <stdint.h>

#define BSZ  4096
#define HDIM 1024
#define NL1  28
#define NL2  280
#define NL3  2800

// Padded weight rows: 128 (L1) + 384 (L2) + 2816 (L3)
#define PR1   128
#define PR2   384
#define PR3   2816
#define PROWS (PR1 + PR2 + PR3)   // 3328

// Scratch (__device__ globals; allocation-free rule)
__device__ __half g_xh[(size_t)BSZ * HDIM];      // fp16 X
__device__ __half g_wh[(size_t)PROWS * HDIM];    // fp16 padded W
__device__ float  g_bp[PROWS];                   // padded bias (fp32)
__device__ float  g_z1[BSZ * NL1];
__device__ float  g_z2[BSZ * NL2];
__device__ float  g_z3[(size_t)BSZ * NL3];
__device__ unsigned long long g_loss_acc;        // fixed-point loss accumulator
__device__ unsigned int      g_done_ctr;         // block completion ticket

#define LOSS_SCALE 68719476736.0   // 2^36

__device__ __forceinline__ float fast_sigmoid(float t) {
    return __fdividef(1.f, 1.f + __expf(-t));
}

// ---------------------------------------------------------------------------
// Conversion: X -> g_xh (fp16 RN), {W1,W2,W3} -> g_wh (fp16, padded with 0),
// {b1,b2,b3} -> g_bp. Also resets the loss accumulator/ticket.
// ---------------------------------------------------------------------------
#define NX4 (BSZ * HDIM / 4)        // 1048576
#define NW4 (PROWS * HDIM / 4)      // 851968
#define H4  (HDIM / 4)              // 256

__device__ __forceinline__ void store_h4(__half* dst, float4 v) {
    __half2 lo = __floats2half2_rn(v.x, v.y);
    __half2 hi = __floats2half2_rn(v.z, v.w);
    uint2 p;
    p.x = *(uint32_t*)&lo;
    p.y = *(uint32_t*)&hi;
    *(uint2*)dst = p;
}

__global__ __launch_bounds__(256) void convert_kernel(
    const float* __restrict__ X,
    const float* __restrict__ W1, const float* __restrict__ W2,
    const float* __restrict__ W3,
    const float* __restrict__ b1, const float* __restrict__ b2,
    const float* __restrict__ b3)
{
    int gid = blockIdx.x * 256 + threadIdx.x;

    if (gid == 0) { g_loss_acc = 0ull; g_done_ctr = 0u; }

    if (gid < NX4) {
        float4 v = ((const float4*)X)[gid];
        store_h4(g_xh + (size_t)gid * 4, v);
    } else if (gid < NX4 + NW4) {
        int wi = gid - NX4;
        int pr = wi / H4;
        int c  = wi - pr * H4;
        float4 v = make_float4(0.f, 0.f, 0.f, 0.f);
        if (pr < PR1) {
            if (pr < NL1) v = ((const float4*)W1)[pr * H4 + c];
        } else if (pr < PR1 + PR2) {
            int r = pr - PR1;
            if (r < NL2) v = ((const float4*)W2)[r * H4 + c];
        } else {
            int r = pr - PR1 - PR2;
            if (r < NL3) v = ((const float4*)W3)[(size_t)r * H4 + c];
        }
        store_h4(g_wh + (size_t)wi * 4, v);
    }

    if (gid < PROWS) {
        float b = 0.f;
        if (gid < PR1) {
            if (gid < NL1) b = b1[gid];
        } else if (gid < PR1 + PR2) {
            int r = gid - PR1;
            if (r < NL2) b = b2[r];
        } else {
            int r = gid - PR1 - PR2;
            if (r < NL3) b = b3[r];
        }
        g_bp[gid] = b;
    }
}

// ---------------------------------------------------------------------------
// Fused fp16 tensor GEMM + bias + sigmoid for all three levels.
// Tiles 128x128x32(halves), 256 threads, warp tile 64x32,
// mma.m16n8k16.f32.f16.f16.f32. 3-stage cp.async pipeline, inputs pre-padded.
// Smem rows stride 40 halves (80B): half2 fragment loads conflict-free.
// ---------------------------------------------------------------------------
#define BM 128
#define BN 128
#define BK 32
#define SKS 40
#define STAGE_H (2 * 128 * SKS)       // 10240
#define STAGE_BYTES (STAGE_H * 2)     // 20480
#define SMEM_BYTES (3 * STAGE_BYTES)  // 61440
#define B_OFF_H (128 * SKS)           // 5120

#define CP_ASYNC16(dst_u32, src_ptr) \
    asm volatile("cp.async.cg.shared.global [%0], [%1], 16;" :: "r"(dst_u32), "l"(src_ptr))

__global__ __launch_bounds__(256, 2) void gemm_fused_kernel()
{
    extern __shared__ __half sm[];

    const int tile = blockIdx.x;      // 0..25
    int bn, woff, N;
    float* __restrict__ Z;
    if (tile == 0)      { bn = 0;               woff = 0;         N = NL1; Z = g_z1; }
    else if (tile < 4)  { bn = (tile - 1) * BN; woff = PR1;       N = NL2; Z = g_z2; }
    else                { bn = (tile - 4) * BN; woff = PR1 + PR2; N = NL3; Z = g_z3; }

    const int bm   = blockIdx.y * BM;
    const int tid  = threadIdx.x;
    const int warp = tid >> 5;
    const int lane = tid & 31;
    const int g    = lane >> 2;
    const int t    = lane & 3;
    const int wm   = (warp >> 2) * 64;
    const int wn   = (warp & 3) * 32;

    const __half* __restrict__ Xt = g_xh + (size_t)bm * HDIM;
    const __half* __restrict__ Wt = g_wh + (size_t)(woff + bn) * HDIM;

    const uint32_t sbase = (uint32_t)__cvta_generic_to_shared(sm);

    const int r0 = tid >> 2;
    const int c0 = tid & 3;

    float acc[4][4][4];
#pragma unroll
    for (int mt = 0; mt < 4; mt++)
#pragma unroll
        for (int nt = 0; nt < 4; nt++)
#pragma unroll
            for (int c = 0; c < 4; c++) acc[mt][nt][c] = 0.f;

    auto issue_stage = [&](int buf, int k0) {
        uint32_t so = sbase + (uint32_t)buf * STAGE_BYTES;
#pragma unroll
        for (int u = 0; u < 2; u++) {
            int r = r0 + u * 64;
            CP_ASYNC16(so + (uint32_t)(r * 80 + c0 * 16),
                       Xt + (size_t)r * HDIM + k0 + c0 * 8);
            CP_ASYNC16(so + (uint32_t)(B_OFF_H * 2 + r * 80 + c0 * 16),
                       Wt + (size_t)r * HDIM + k0 + c0 * 8);
        }
    };

    issue_stage(0, 0);
    asm volatile("cp.async.commit_group;");
    issue_stage(1, BK);
    asm volatile("cp.async.commit_group;");

    const int NIT = HDIM / BK;        // 32
    for (int it = 0; it < NIT; it++) {
        asm volatile("cp.async.wait_group 1;");
        __syncthreads();

        if (it + 2 < NIT) issue_stage((it + 2) % 3, (it + 2) * BK);
        asm volatile("cp.async.commit_group;");

        const __half* A = sm + (it % 3) * STAGE_H;
        const __half* B = A + B_OFF_H;

#pragma unroll
        for (int kk = 0; kk < BK; kk += 16) {
            uint32_t afr[4][4], bfr[4][2];
#pragma unroll
            for (int mt = 0; mt < 4; mt++) {
                int m0 = wm + mt * 16 + g;
                afr[mt][0] = *(const uint32_t*)&A[m0 * SKS + kk + 2 * t];
                afr[mt][1] = *(const uint32_t*)&A[(m0 + 8) * SKS + kk + 2 * t];
                afr[mt][2] = *(const uint32_t*)&A[m0 * SKS + kk + 2 * t + 8];
                afr[mt][3] = *(const uint32_t*)&A[(m0 + 8) * SKS + kk + 2 * t + 8];
            }
#pragma unroll
            for (int nt = 0; nt < 4; nt++) {
                int n0 = wn + nt * 8 + g;
                bfr[nt][0] = *(const uint32_t*)&B[n0 * SKS + kk + 2 * t];
                bfr[nt][1] = *(const uint32_t*)&B[n0 * SKS + kk + 2 * t + 8];
            }
#pragma unroll
            for (int mt = 0; mt < 4; mt++)
#pragma unroll
                for (int nt = 0; nt < 4; nt++) {
                    asm volatile(
                        "mma.sync.aligned.m16n8k16.row.col.f32.f16.f16.f32 "
                        "{%0,%1,%2,%3}, {%4,%5,%6,%7}, {%8,%9}, {%0,%1,%2,%3};"
                        : "+f"(acc[mt][nt][0]), "+f"(acc[mt][nt][1]),
                          "+f"(acc[mt][nt][2]), "+f"(acc[mt][nt][3])
                        : "r"(afr[mt][0]), "r"(afr[mt][1]),
                          "r"(afr[mt][2]), "r"(afr[mt][3]),
                          "r"(bfr[nt][0]), "r"(bfr[nt][1]));
                }
        }
    }

    const float* __restrict__ bt = g_bp + woff + bn;
#pragma unroll
    for (int mt = 0; mt < 4; mt++) {
#pragma unroll
        for (int nt = 0; nt < 4; nt++) {
#pragma unroll
            for (int c = 0; c < 4; c++) {
                int m  = bm + wm + mt * 16 + g + ((c >= 2) ? 8 : 0);
                int nl = wn + nt * 8 + 2 * t + (c & 1);
                int n  = bn + nl;
                if (n < N) {
                    float v = acc[mt][nt][c] + bt[nl];
                    Z[(size_t)m * N + n] = fast_sigmoid(v);
                }
            }
        }
    }
}

// ---------------------------------------------------------------------------
// Per-row path products + losses. Gathers z3[k/100], z3[k/10] touch only
// indices 0..279 -> stage just z3[0:280] in smem and stream the rest from
// global (.cs hints). Per-row loss accumulated in 2^36 fixed point via
// integer atomics (associative -> deterministic); last block writes mean.
// ---------------------------------------------------------------------------
__global__ __launch_bounds__(256) void path_loss_kernel(
    const int* __restrict__ labels,
    float* __restrict__ out_logits,
    float* __restrict__ loss_out,
    int write_logits)
{
    const int b    = blockIdx.x;
    const int tid  = threadIdx.x;
    const int lane = tid & 31;
    const int warp = tid >> 5;

    __shared__ float sg[NL2];   // z3[0:280] (covers all gather indices)
    __shared__ float s2[NL2];
    __shared__ float s1[NL1];
    __shared__ float red3[8], red2[8], red1[8];

    const float* __restrict__ z3row = g_z3 + (size_t)b * NL3;

    if (tid < NL2 / 4) {
        ((float4*)sg)[tid] = ((const float4*)z3row)[tid];
        ((float4*)s2)[tid] = ((const float4*)(g_z2 + b * NL2))[tid];
    }
    if (tid < NL1)
        s1[tid] = g_z1[b * NL1 + tid];
    __syncthreads();

    // level 3: stream z3 row from global, gather prefixes from smem
    float sum3 = 0.f;
    for (int k4 = tid; k4 < NL3 / 4; k4 += 256) {
        int k = k4 * 4;
        float4 zk = __ldcs((const float4*)z3row + k4);
        float4 l;
        l.x = sg[k / 100]       * sg[k / 10]       * zk.x;
        l.y = sg[(k + 1) / 100] * sg[(k + 1) / 10] * zk.y;
        l.z = sg[(k + 2) / 100] * sg[(k + 2) / 10] * zk.z;
        l.w = sg[(k + 3) / 100] * sg[(k + 3) / 10] * zk.w;
        if (write_logits)
            __stcs((float4*)(out_logits + (size_t)b * NL3) + k4, l);
        sum3 += __expf(l.x) + __expf(l.y) + __expf(l.z) + __expf(l.w);
    }
#pragma unroll
    for (int off = 16; off; off >>= 1) sum3 += __shfl_xor_sync(0xffffffffu, sum3, off);
    if (lane == 0) red3[warp] = sum3;

    // level 2
    {
        float s = 0.f;
        if (tid < NL2 / 4) {
            int k = tid * 4;
            float4 zk = ((const float4*)s2)[tid];
            s = __expf(s2[k / 10] * zk.x) + __expf(s2[(k + 1) / 10] * zk.y) +
                __expf(s2[(k + 2) / 10] * zk.z) + __expf(s2[(k + 3) / 10] * zk.w);
        }
#pragma unroll
        for (int off = 16; off; off >>= 1) s += __shfl_xor_sync(0xffffffffu, s, off);
        if (lane == 0) red2[warp] = s;
    }
    // level 1
    {
        float s = (tid < NL1) ? __expf(s1[tid]) : 0.f;
#pragma unroll
        for (int off = 16; off; off >>= 1) s += __shfl_xor_sync(0xffffffffu, s, off);
        if (lane == 0) red1[warp] = s;
    }
    __syncthreads();

    if (tid == 0) {
        float t3 = 0.f, t2 = 0.f, t1 = 0.f;
#pragma unroll
        for (int w = 0; w < 8; w++) { t3 += red3[w]; t2 += red2[w]; t1 += red1[w]; }
        int lab = labels[b];
        int a1 = lab / 100;
        int a2 = lab / 10;
        float l3 = sg[a1] * sg[a2] * z3row[lab];
        float l2 = s2[a1] * s2[a2];
        float l1 = s1[a1];
        float loss = (logf(t1) - l1) + (logf(t2) - l2) + (logf(t3) - l3);

        // deterministic integer accumulation (loss > 0 always)
        unsigned long long q = (unsigned long long)((double)loss * LOSS_SCALE);
        atomicAdd(&g_loss_acc, q);
        __threadfence();
        unsigned int ticket = atomicAdd(&g_done_ctr, 1u);
        if (ticket == BSZ - 1) {
            unsigned long long total = atomicAdd(&g_loss_acc, 0ull);
            if (loss_out)
                *loss_out = (float)((double)total / LOSS_SCALE / (double)BSZ);
        }
    }
}

// ---------------------------------------------------------------------------
extern "C" void kernel_launch(void* const* d_in, const int* in_sizes, int n_in,
                              void* d_out, int out_size)
{
    const float* x      = (const float*)d_in[0];
    const int*   labels = (const int*)  d_in[1];
    const float* W1     = (const float*)d_in[2];
    const float* b1     = (const float*)d_in[3];
    const float* W2     = (const float*)d_in[4];
    const float* b2     = (const float*)d_in[5];
    const float* W3     = (const float*)d_in[6];
    const float* b3     = (const float*)d_in[7];
    float* out = (float*)d_out;

    static int smem_set = 0;
    if (!smem_set) {
        cudaFuncSetAttribute(gemm_fused_kernel,
                             cudaFuncAttributeMaxDynamicSharedMemorySize, SMEM_BYTES);
        smem_set = 1;
    }

    int conv_blocks = (NX4 + NW4 + 255) / 256;
    convert_kernel<<<conv_blocks, 256>>>(x, W1, W2, W3, b1, b2, b3);

    gemm_fused_kernel<<<dim3(26, BSZ / BM), 256, SMEM_BYTES>>>();

    const long long need = (long long)BSZ * NL3;
    int write_logits = (out_size >= need) ? 1 : 0;
    float* loss_ptr = nullptr;
    if (out_size == 1)                      loss_ptr = out;
    else if ((long long)out_size >= need+1) loss_ptr = out + need;

    path_loss_kernel<<<BSZ, 256>>>(labels, write_logits ? out : nullptr,
                                   loss_ptr, write_logits);
}

// round 16
// speedup vs baseline: 6.3059x; 1.0136x over previous
#include <cuda_runtime.h>
#include <cuda_fp16.h>
#include <math.h>
#include <stdint.h>

#define BSZ  4096
#define HDIM 1024
#define NL1  28
#define NL2  280
#define NL3  2800

// Padded weight rows: 128 (L1) + 384 (L2) + 2816 (L3)
#define PR1   128
#define PR2   384
#define PR3   2816
#define PROWS (PR1 + PR2 + PR3)   // 3328
// packed-z offsets (match padded weight layout)
#define ZO1 0
#define ZO2 PR1            // 128
#define ZO3 (PR1 + PR2)    // 512

// Scratch (__device__ globals; allocation-free rule)
__device__ __half g_xh[(size_t)BSZ * HDIM];      // fp16 X
__device__ __half g_wh[(size_t)PROWS * HDIM];    // fp16 padded W
__device__ float  g_bp[PROWS];                   // padded bias (fp32)
__device__ float  g_zp[(size_t)BSZ * PROWS];     // packed sigmoid outputs
__device__ unsigned long long g_loss_acc;        // fixed-point loss accumulator
__device__ unsigned int      g_done_ctr;         // block completion ticket

#define LOSS_SCALE 68719476736.0   // 2^36

__device__ __forceinline__ float fast_sigmoid(float t) {
    return __fdividef(1.f, 1.f + __expf(-t));
}

// ---------------------------------------------------------------------------
// Conversion: X -> g_xh (fp16), {W1,W2,W3} -> g_wh (fp16, padded with 0),
// {b1,b2,b3} -> g_bp. 4 float4 slots per thread for MLP. Resets accumulators.
// ---------------------------------------------------------------------------
#define NX4 (BSZ * HDIM / 4)        // 1048576
#define NW4 (PROWS * HDIM / 4)      // 851968
#define H4  (HDIM / 4)              // 256

__device__ __forceinline__ void store_h4(__half* dst, float4 v) {
    __half2 lo = __floats2half2_rn(v.x, v.y);
    __half2 hi = __floats2half2_rn(v.z, v.w);
    uint2 p;
    p.x = *(uint32_t*)&lo;
    p.y = *(uint32_t*)&hi;
    *(uint2*)dst = p;
}

__global__ __launch_bounds__(256) void convert_kernel(
    const float* __restrict__ X,
    const float* __restrict__ W1, const float* __restrict__ W2,
    const float* __restrict__ W3,
    const float* __restrict__ b1, const float* __restrict__ b2,
    const float* __restrict__ b3)
{
    const int tid  = threadIdx.x;
    const int base = blockIdx.x * 1024 + tid;

#pragma unroll
    for (int i = 0; i < 4; i++) {
        int gid = base + i * 256;
        if (gid < NX4) {
            float4 v = ((const float4*)X)[gid];
            store_h4(g_xh + (size_t)gid * 4, v);
        } else if (gid < NX4 + NW4) {
            int wi = gid - NX4;
            int pr = wi / H4;
            int c  = wi - pr * H4;
            float4 v = make_float4(0.f, 0.f, 0.f, 0.f);
            if (pr < PR1) {
                if (pr < NL1) v = ((const float4*)W1)[pr * H4 + c];
            } else if (pr < PR1 + PR2) {
                int r = pr - PR1;
                if (r < NL2) v = ((const float4*)W2)[r * H4 + c];
            } else {
                int r = pr - PR1 - PR2;
                if (r < NL3) v = ((const float4*)W3)[(size_t)r * H4 + c];
            }
            store_h4(g_wh + (size_t)wi * 4, v);
        }
    }

    if (blockIdx.x == 0) {
        for (int j = tid; j < PROWS; j += 256) {
            float b = 0.f;
            if (j < PR1) {
                if (j < NL1) b = b1[j];
            } else if (j < PR1 + PR2) {
                int r = j - PR1;
                if (r < NL2) b = b2[r];
            } else {
                int r = j - PR1 - PR2;
                if (r < NL3) b = b3[r];
            }
            g_bp[j] = b;
        }
        if (tid == 0) { g_loss_acc = 0ull; g_done_ctr = 0u; }
    }
}

// ---------------------------------------------------------------------------
// Fused fp16 tensor GEMM + bias + sigmoid, packed padded output.
// Tiles 128x128x32(halves), 256 threads, warp tile 64x32,
// mma.m16n8k16.f32.f16.f16.f32. 3-stage cp.async pipeline, inputs pre-padded.
// Smem rows stride 40 halves (80B): half2 fragment loads conflict-free.
// Epilogue: branch-free float2 stores into g_zp[B][3328].
// ---------------------------------------------------------------------------
#define BM 128
#define BN 128
#define BK 32
#define SKS 40
#define STAGE_H (2 * 128 * SKS)       // 10240
#define STAGE_BYTES (STAGE_H * 2)     // 20480
#define SMEM_BYTES (3 * STAGE_BYTES)  // 61440
#define B_OFF_H (128 * SKS)           // 5120

#define CP_ASYNC16(dst_u32, src_ptr) \
    asm volatile("cp.async.cg.shared.global [%0], [%1], 16;" :: "r"(dst_u32), "l"(src_ptr))

__global__ __launch_bounds__(256, 2) void gemm_fused_kernel()
{
    extern __shared__ __half sm[];

    const int bn   = blockIdx.x * BN;    // padded col offset (0..25*128)
    const int bm   = blockIdx.y * BM;
    const int tid  = threadIdx.x;
    const int warp = tid >> 5;
    const int lane = tid & 31;
    const int g    = lane >> 2;
    const int t    = lane & 3;
    const int wm   = (warp >> 2) * 64;
    const int wn   = (warp & 3) * 32;

    const __half* __restrict__ Xt = g_xh + (size_t)bm * HDIM;
    const __half* __restrict__ Wt = g_wh + (size_t)bn * HDIM;

    const uint32_t sbase = (uint32_t)__cvta_generic_to_shared(sm);

    const int r0 = tid >> 2;
    const int c0 = tid & 3;

    float acc[4][4][4];
#pragma unroll
    for (int mt = 0; mt < 4; mt++)
#pragma unroll
        for (int nt = 0; nt < 4; nt++)
#pragma unroll
            for (int c = 0; c < 4; c++) acc[mt][nt][c] = 0.f;

    auto issue_stage = [&](int buf, int k0) {
        uint32_t so = sbase + (uint32_t)buf * STAGE_BYTES;
#pragma unroll
        for (int u = 0; u < 2; u++) {
            int r = r0 + u * 64;
            CP_ASYNC16(so + (uint32_t)(r * 80 + c0 * 16),
                       Xt + (size_t)r * HDIM + k0 + c0 * 8);
            CP_ASYNC16(so + (uint32_t)(B_OFF_H * 2 + r * 80 + c0 * 16),
                       Wt + (size_t)r * HDIM + k0 + c0 * 8);
        }
    };

    issue_stage(0, 0);
    asm volatile("cp.async.commit_group;");
    issue_stage(1, BK);
    asm volatile("cp.async.commit_group;");

    const int NIT = HDIM / BK;        // 32
    for (int it = 0; it < NIT; it++) {
        asm volatile("cp.async.wait_group 1;");
        __syncthreads();

        if (it + 2 < NIT) issue_stage((it + 2) % 3, (it + 2) * BK);
        asm volatile("cp.async.commit_group;");

        const __half* A = sm + (it % 3) * STAGE_H;
        const __half* B = A + B_OFF_H;

#pragma unroll
        for (int kk = 0; kk < BK; kk += 16) {
            uint32_t afr[4][4], bfr[4][2];
#pragma unroll
            for (int mt = 0; mt < 4; mt++) {
                int m0 = wm + mt * 16 + g;
                afr[mt][0] = *(const uint32_t*)&A[m0 * SKS + kk + 2 * t];
                afr[mt][1] = *(const uint32_t*)&A[(m0 + 8) * SKS + kk + 2 * t];
                afr[mt][2] = *(const uint32_t*)&A[m0 * SKS + kk + 2 * t + 8];
                afr[mt][3] = *(const uint32_t*)&A[(m0 + 8) * SKS + kk + 2 * t + 8];
            }
#pragma unroll
            for (int nt = 0; nt < 4; nt++) {
                int n0 = wn + nt * 8 + g;
                bfr[nt][0] = *(const uint32_t*)&B[n0 * SKS + kk + 2 * t];
                bfr[nt][1] = *(const uint32_t*)&B[n0 * SKS + kk + 2 * t + 8];
            }
#pragma unroll
            for (int mt = 0; mt < 4; mt++)
#pragma unroll
                for (int nt = 0; nt < 4; nt++) {
                    asm volatile(
                        "mma.sync.aligned.m16n8k16.row.col.f32.f16.f16.f32 "
                        "{%0,%1,%2,%3}, {%4,%5,%6,%7}, {%8,%9}, {%0,%1,%2,%3};"
                        : "+f"(acc[mt][nt][0]), "+f"(acc[mt][nt][1]),
                          "+f"(acc[mt][nt][2]), "+f"(acc[mt][nt][3])
                        : "r"(afr[mt][0]), "r"(afr[mt][1]),
                          "r"(afr[mt][2]), "r"(afr[mt][3]),
                          "r"(bfr[nt][0]), "r"(bfr[nt][1]));
                }
        }
    }

    // branch-free epilogue: bias + sigmoid, float2 stores into packed Z
    const float* __restrict__ bb = g_bp + bn;
#pragma unroll
    for (int mt = 0; mt < 4; mt++) {
        const int m0 = bm + wm + mt * 16 + g;
#pragma unroll
        for (int nt = 0; nt < 4; nt++) {
            const int nl = wn + nt * 8 + 2 * t;
            const float b0 = bb[nl];
            const float b1 = bb[nl + 1];
            float2 v;
            v.x = fast_sigmoid(acc[mt][nt][0] + b0);
            v.y = fast_sigmoid(acc[mt][nt][1] + b1);
            *(float2*)(g_zp + (size_t)m0 * PROWS + bn + nl) = v;
            v.x = fast_sigmoid(acc[mt][nt][2] + b0);
            v.y = fast_sigmoid(acc[mt][nt][3] + b1);
            *(float2*)(g_zp + (size_t)(m0 + 8) * PROWS + bn + nl) = v;
        }
    }
}

// ---------------------------------------------------------------------------
// Per-row path products + losses.
// pre[j] = z3[j/10]*z3[j] (j<280) -> logits3[k] = pre[k/10]*z3[k].
// NOTE: NL2=280 > blockDim=256, so all smem staging uses strided loops.
// z3 row streamed from global (.cs); loss accumulated in 2^36 fixed point
// via integer atomics (associative -> deterministic); last block writes mean.
// ---------------------------------------------------------------------------
__global__ __launch_bounds__(256) void path_loss_kernel(
    const int* __restrict__ labels,
    float* __restrict__ out_logits,
    float* __restrict__ loss_out,
    int write_logits)
{
    const int b    = blockIdx.x;
    const int tid  = threadIdx.x;
    const int lane = tid & 31;
    const int warp = tid >> 5;

    __shared__ float pre[NL2];  // level-3 prefix products
    __shared__ float s2[NL2];
    __shared__ float s1[NL1];
    __shared__ float red3[8], red2[8], red1[8];

    const float* __restrict__ zrow  = g_zp + (size_t)b * PROWS;
    const float* __restrict__ z3row = zrow + ZO3;

    // strided staging: covers ALL 280 entries with 256 threads
    for (int j = tid; j < NL2; j += 256) {
        pre[j] = z3row[j / 10] * z3row[j];
        s2[j]  = zrow[ZO2 + j];
    }
    if (tid < NL1)
        s1[tid] = zrow[ZO1 + tid];
    __syncthreads();

    // level 3: stream z3 row, gather prefix product from smem
    float sum3 = 0.f;
    for (int k4 = tid; k4 < NL3 / 4; k4 += 256) {
        int k = k4 * 4;
        float4 zk = __ldcs((const float4*)z3row + k4);
        float4 l;
        l.x = pre[k / 10]       * zk.x;
        l.y = pre[(k + 1) / 10] * zk.y;
        l.z = pre[(k + 2) / 10] * zk.z;
        l.w = pre[(k + 3) / 10] * zk.w;
        if (write_logits)
            __stcs((float4*)(out_logits + (size_t)b * NL3) + k4, l);
        sum3 += __expf(l.x) + __expf(l.y) + __expf(l.z) + __expf(l.w);
    }
#pragma unroll
    for (int off = 16; off; off >>= 1) sum3 += __shfl_xor_sync(0xffffffffu, sum3, off);
    if (lane == 0) red3[warp] = sum3;

    // level 2 (strided: 280 > 256)
    {
        float s = 0.f;
        for (int k = tid; k < NL2; k += 256)
            s += __expf(s2[k / 10] * s2[k]);
#pragma unroll
        for (int off = 16; off; off >>= 1) s += __shfl_xor_sync(0xffffffffu, s, off);
        if (lane == 0) red2[warp] = s;
    }
    // level 1
    {
        float s = (tid < NL1) ? __expf(s1[tid]) : 0.f;
#pragma unroll
        for (int off = 16; off; off >>= 1) s += __shfl_xor_sync(0xffffffffu, s, off);
        if (lane == 0) red1[warp] = s;
    }
    __syncthreads();

    if (tid == 0) {
        float t3 = 0.f, t2 = 0.f, t1 = 0.f;
#pragma unroll
        for (int w = 0; w < 8; w++) { t3 += red3[w]; t2 += red2[w]; t1 += red1[w]; }
        int lab = labels[b];
        int a1 = lab / 100;
        int a2 = lab / 10;
        float l3 = pre[a2] * z3row[lab];
        float l2 = s2[a1] * s2[a2];
        float l1 = s1[a1];
        float loss = (logf(t1) - l1) + (logf(t2) - l2) + (logf(t3) - l3);

        unsigned long long q = (unsigned long long)((double)loss * LOSS_SCALE);
        atomicAdd(&g_loss_acc, q);
        __threadfence();
        unsigned int ticket = atomicAdd(&g_done_ctr, 1u);
        if (ticket == BSZ - 1) {
            unsigned long long total = atomicAdd(&g_loss_acc, 0ull);
            if (loss_out)
                *loss_out = (float)((double)total / LOSS_SCALE / (double)BSZ);
        }
    }
}

// ---------------------------------------------------------------------------
extern "C" void kernel_launch(void* const* d_in, const int* in_sizes, int n_in,
                              void* d_out, int out_size)
{
    const float* x      = (const float*)d_in[0];
    const int*   labels = (const int*)  d_in[1];
    const float* W1     = (const float*)d_in[2];
    const float* b1     = (const float*)d_in[3];
    const float* W2     = (const float*)d_in[4];
    const float* b2     = (const float*)d_in[5];
    const float* W3     = (const float*)d_in[6];
    const float* b3     = (const float*)d_in[7];
    float* out = (float*)d_out;

    static int smem_set = 0;
    if (!smem_set) {
        cudaFuncSetAttribute(gemm_fused_kernel,
                             cudaFuncAttributeMaxDynamicSharedMemorySize, SMEM_BYTES);
        smem_set = 1;
    }

    int conv_blocks = (NX4 + NW4 + 1023) / 1024;
    convert_kernel<<<conv_blocks, 256>>>(x, W1, W2, W3, b1, b2, b3);

    gemm_fused_kernel<<<dim3(PROWS / BN, BSZ / BM), 256, SMEM_BYTES>>>();

    const long long need = (long long)BSZ * NL3;
    int write_logits = (out_size >= need) ? 1 : 0;
    float* loss_ptr = nullptr;
    if (out_size == 1)                        loss_ptr = out;
    else if ((long long)out_size >= need + 1) loss_ptr = out + need;

    path_loss_kernel<<<BSZ, 256>>>(labels, write_logits ? out : nullptr,
                                   loss_ptr, write_logits);
}